// round 13
// baseline (speedup 1.0000x reference)
#include <cuda_runtime.h>
#include <cuda_fp16.h>
#include <cstdint>
#include <cstddef>

#define B_ 256
#define T_ 512
#define H_ 256
#define I_ 64
#define CSZ 8
#define MR 16
#define NLOC 128
#define TCH 32

// ---------------- device scratch ----------------
__device__ float  g_h2last[B_ * H_];
__device__ __half g_whh0[CSZ * NLOC * 256];    // L0 recurrent weights, rank-sliced, gate-interleaved
__device__ __half g_w1cat[CSZ * NLOC * 512];   // L1 [Whh1|Wih1] rows, rank-sliced, gate-interleaved
__device__ __half g_wih0[CSZ * NLOC * 64];
__device__ float  g_bias0[CSZ * NLOC];
__device__ float  g_bias1[CSZ * NLOC];
// Precomputed L0 input-gate terms (bias folded): [cta(128), t(512), slot(256), 8]
// slot = warp*32+lane of the consumer; 8 floats = i0,i1,f0,f1,g0,g1,o0,o1 for cols (c0,c0+1)
__device__ float  g_xg0[(size_t)128 * 512 * 256 * 8];

// ---------------- helpers ----------------
__device__ __forceinline__ unsigned su32(const void* p) {
    unsigned a;
    asm("{ .reg .u64 t; cvta.to.shared.u64 t, %1; cvt.u32.u64 %0, t; }" : "=r"(a) : "l"(p));
    return a;
}
__device__ __forceinline__ float tanhap(float x) {
    float y;
    asm("tanh.approx.f32 %0, %1;" : "=f"(y) : "f"(x));
    return y;
}
__device__ __forceinline__ float sigm(float x) {
    return fmaf(tanhap(0.5f * x), 0.5f, 0.5f);
}
__device__ __forceinline__ void ldsm_x2(uint32_t& b0, uint32_t& b1, unsigned a) {
    asm volatile("ldmatrix.sync.aligned.m8n8.x2.shared.b16 {%0,%1}, [%2];"
                 : "=r"(b0), "=r"(b1) : "r"(a));
}
__device__ __forceinline__ void ldsm_x4(uint32_t* r, unsigned a) {
    asm volatile("ldmatrix.sync.aligned.m8n8.x4.shared.b16 {%0,%1,%2,%3}, [%4];"
                 : "=r"(r[0]), "=r"(r[1]), "=r"(r[2]), "=r"(r[3]) : "r"(a));
}
__device__ __forceinline__ void mma16816(float* acc, const uint32_t* a, uint32_t b0, uint32_t b1) {
    asm volatile(
        "mma.sync.aligned.m16n8k16.row.col.f32.f16.f16.f32 "
        "{%0,%1,%2,%3}, {%4,%5,%6,%7}, {%8,%9}, {%0,%1,%2,%3};"
        : "+f"(acc[0]), "+f"(acc[1]), "+f"(acc[2]), "+f"(acc[3])
        : "r"(a[0]), "r"(a[1]), "r"(a[2]), "r"(a[3]), "r"(b0), "r"(b1));
}

// ---------------- weight prep (gate-INTERLEAVED rows) ----------------
// Local row l of rank r: h-col c = l>>2, gate g = l&3, grow = g*256 + r*32 + c.
__global__ void prep_kernel(const float* __restrict__ Wih0, const float* __restrict__ Whh0,
                            const float* __restrict__ bih0, const float* __restrict__ bhh0,
                            const float* __restrict__ Wih1, const float* __restrict__ Whh1,
                            const float* __restrict__ bih1, const float* __restrict__ bhh1) {
    int blk = blockIdx.x;
    int li = blk & 1023;
    int r = li >> 7, l = li & 127;
    int c = l >> 2, g = l & 3;
    int grow = g * H_ + r * 32 + c;
    if (blk < 1024) {
        for (int k = threadIdx.x; k < 256; k += blockDim.x)
            g_whh0[(r * NLOC + l) * 256 + k] = __float2half_rn(Whh0[grow * H_ + k]);
        for (int k = threadIdx.x; k < 64; k += blockDim.x)
            g_wih0[(r * NLOC + l) * 64 + k] = __float2half_rn(Wih0[grow * I_ + k]);
        if (threadIdx.x == 0) g_bias0[r * NLOC + l] = bih0[grow] + bhh0[grow];
    } else {
        for (int k = threadIdx.x; k < 512; k += blockDim.x) {
            float v = (k < 256) ? Whh1[grow * H_ + k] : Wih1[grow * H_ + (k - 256)];
            g_w1cat[(r * NLOC + l) * 512 + k] = __float2half_rn(v);
        }
        if (threadIdx.x == 0) g_bias1[r * NLOC + l] = bih1[grow] + bhh1[grow];
    }
}

// ---------------- time-parallel L0 input GEMM ----------------
__global__ void __launch_bounds__(256) xg_gemm64(const float* __restrict__ xin) {
    constexpr int KT  = 4;
    constexpr int KPB = (64 + 8) * 2;   // 144

    extern __shared__ __align__(16) char smem[];
    char*  sW    = smem;
    char*  sB    = sW + NLOC * KPB;
    float* sG    = (float*)(sB + MR * KPB);
    float* sBias = sG + NLOC * 17;

    const int tid  = threadIdx.x;
    const int wid  = tid >> 5;
    const int lane = tid & 31;
    const int rank = blockIdx.x & 7;
    const int bm0  = (blockIdx.x >> 3) * MR;
    const int t0   = blockIdx.y * TCH;

    {
        const uint4* src = (const uint4*)(g_wih0 + (size_t)rank * NLOC * 64);
        for (int i = tid; i < NLOC * 8; i += 256) {
            int l = i >> 3, c = i & 7;
            *(uint4*)(sW + l * KPB + c * 16) = src[i];
        }
    }
    if (tid < NLOC) sBias[tid] = g_bias0[rank * NLOC + tid];
    __syncthreads();

    uint32_t wreg[KT][4];
    {
        unsigned rb = su32(sW) + (unsigned)(wid * 16 + (lane & 15)) * KPB + ((lane & 16) ? 16u : 0u);
#pragma unroll
        for (int kt = 0; kt < KT; kt++) ldsm_x4(wreg[kt], rb + kt * 32);
    }

    const unsigned sBu = su32(sB);
    const unsigned boffL = (unsigned)((lane & 7) * KPB) + ((lane & 8) ? 16u : 0u);
    const int gid = lane >> 2, ctid = lane & 3;
    const int mx = tid >> 4, cx = tid & 15;
    // epilogue mapping (matches loop consumer): slot tid -> warp w, lane ln
    const int ew = tid >> 5, eln = tid & 31;
    const int ecp = eln >> 4, em = eln & 15;
    const int ec0 = 4 * ew + 2 * ecp;

    for (int tt = 0; tt < TCH; tt++) {
        const int t = t0 + tt;
        float4 v = *(const float4*)&xin[((size_t)(bm0 + mx) * T_ + t) * I_ + cx * 4];
        __half2* d = (__half2*)(sB + mx * KPB + cx * 8);
        d[0] = __floats2half2_rn(v.x, v.y);
        d[1] = __floats2half2_rn(v.z, v.w);
        __syncthreads();

        float accA[2][4] = {{0.f,0.f,0.f,0.f},{0.f,0.f,0.f,0.f}};
#pragma unroll
        for (int nt = 0; nt < 2; nt++) {
            unsigned bb = sBu + (unsigned)(nt * 8) * KPB + boffL;
#pragma unroll
            for (int kt = 0; kt < KT; kt++) {
                uint32_t b0, b1;
                ldsm_x2(b0, b1, bb + kt * 32);
                mma16816(accA[nt], wreg[kt], b0, b1);
            }
        }
#pragma unroll
        for (int nt = 0; nt < 2; nt++) {
            int col = nt * 8 + 2 * ctid;
            int row = wid * 16 + gid;
            sG[row * 17 + col]           = accA[nt][0];
            sG[row * 17 + col + 1]       = accA[nt][1];
            sG[(row + 8) * 17 + col]     = accA[nt][2];
            sG[(row + 8) * 17 + col + 1] = accA[nt][3];
        }
        __syncthreads();
        {
            // consumer-order epilogue: gates i,f,g,o for cols (ec0, ec0+1), batch em
            float4 oA, oB;
            oA.x = sG[(ec0 * 4 + 0) * 17 + em]       + sBias[ec0 * 4 + 0];
            oA.y = sG[((ec0 + 1) * 4 + 0) * 17 + em] + sBias[(ec0 + 1) * 4 + 0];
            oA.z = sG[(ec0 * 4 + 1) * 17 + em]       + sBias[ec0 * 4 + 1];
            oA.w = sG[((ec0 + 1) * 4 + 1) * 17 + em] + sBias[(ec0 + 1) * 4 + 1];
            oB.x = sG[(ec0 * 4 + 2) * 17 + em]       + sBias[ec0 * 4 + 2];
            oB.y = sG[((ec0 + 1) * 4 + 2) * 17 + em] + sBias[(ec0 + 1) * 4 + 2];
            oB.z = sG[(ec0 * 4 + 3) * 17 + em]       + sBias[ec0 * 4 + 3];
            oB.w = sG[((ec0 + 1) * 4 + 3) * 17 + em] + sBias[(ec0 + 1) * 4 + 3];
            size_t base = (((size_t)blockIdx.x * T_ + t) * 256 + tid) * 8;
            *(float4*)&g_xg0[base]     = oA;
            *(float4*)&g_xg0[base + 4] = oB;
        }
        __syncthreads();
    }
}

// ---------------- fused 2-layer wavefront loop (warp-independent supersteps) ----------------
// Cluster of 8 CTAs = one batch group (16 rows). Gate-interleaved rows: warp wm owns
// all 4 gates for h-cols [4wm, 4wm+4) — GEMM, exchange, cell math and publish are
// warp-local. ONLY sync per superstep is the cluster barrier.
__global__ void __launch_bounds__(256, 1) __cluster_dims__(CSZ, 1, 1)
lstm_fused() {
    constexpr int W1B = 1040;                 // W1cat / hcat row stride bytes (520 halves)
    constexpr int HCB = MR * W1B;             // one hcat buffer = 16640 B
    constexpr int HC_OFF  = 0;                // runtime hcat overlays dead staging
    constexpr int SG0_OFF = 2 * HCB;          // 33280
    constexpr int SG1_OFF = SG0_OFF + NLOC * 17 * 4;   // 41984
    constexpr int SB1_OFF = SG1_OFF + NLOC * 17 * 4;   // 50688
    // staging (init-only): W1cat rows at stride 1040 over [0,133120); Whh0 at 528 over [0,67584)

    extern __shared__ __align__(16) char smem[];
    char*  sHC = smem + HC_OFF;
    float* sG0 = (float*)(smem + SG0_OFF);
    float* sG1 = (float*)(smem + SG1_OFF);
    float* sB1 = (float*)(smem + SB1_OFF);

    const int tid  = threadIdx.x;
    const int wm   = tid >> 5;
    const int lane = tid & 31;
    unsigned rank;
    asm("mov.u32 %0, %%cluster_ctarank;" : "=r"(rank));
    const int bm0 = (blockIdx.x >> 3) * MR;

    // ---- Phase A: stage W1cat, grab wreg1 ----
    {
        const uint4* src = (const uint4*)(g_w1cat + (size_t)rank * NLOC * 512);
        for (int i = tid; i < NLOC * 64; i += 256) {
            int l = i >> 6, c = i & 63;
            *(uint4*)(smem + l * W1B + c * 16) = src[i];
        }
    }
    __syncthreads();
    uint32_t wreg1[32][4];
    {
        unsigned rb = su32(smem) + (unsigned)(wm * 16 + (lane & 15)) * W1B + ((lane & 16) ? 16u : 0u);
#pragma unroll
        for (int kt = 0; kt < 32; kt++) ldsm_x4(wreg1[kt], rb + kt * 32);
    }
    __syncthreads();

    // ---- Phase B: stage Whh0, grab wreg0 ----
    {
        const uint4* s0 = (const uint4*)(g_whh0 + (size_t)rank * NLOC * 256);
        for (int i = tid; i < NLOC * 32; i += 256) {
            int l = i >> 5, c = i & 31;
            *(uint4*)(smem + l * 528 + c * 16) = s0[i];
        }
    }
    __syncthreads();
    uint32_t wreg0[16][4];
    {
        unsigned rb = su32(smem) + (unsigned)(wm * 16 + (lane & 15)) * 528 + ((lane & 16) ? 16u : 0u);
#pragma unroll
        for (int kt = 0; kt < 16; kt++) ldsm_x4(wreg0[kt], rb + kt * 32);
    }
    __syncthreads();

    // ---- Phase C: zero hcat buffers (staging dead), load bias ----
    for (int i = tid; i < 2 * HCB / 4; i += 256) ((unsigned*)sHC)[i] = 0u;
    if (tid < NLOC) sB1[tid] = g_bias1[rank * NLOC + tid];

    const unsigned sHCu  = su32(sHC);
    const unsigned hoffL = (unsigned)((lane & 7) * W1B) + ((lane & 8) ? 16u : 0u);
    const int gid = lane >> 2, ctid = lane & 3;
    // cell mapping: this lane owns cols (c0, c0+1) of the rank's 32, batch row m
    const int cp = lane >> 4, m = lane & 15;
    const int c0 = 4 * wm + 2 * cp;
    // publish offsets within a buffer: h1 slot at +0, h0 slot at +512 within the row
    const unsigned offh = sHCu + (unsigned)(m * W1B + (rank * 32 + c0) * 2);
    const unsigned offx = offh + 512u;

    // xg0 stream (slot tid)
    const float4* xg4 = (const float4*)g_xg0;
    const size_t xbase = ((size_t)blockIdx.x * T_) * 512 + tid * 2;
    float4 xgA = xg4[xbase], xgB = xg4[xbase + 1];

    float c00 = 0.f, c01 = 0.f, c10 = 0.f, c11 = 0.f;

    __syncthreads();
    asm volatile("barrier.cluster.arrive.aligned;" ::: "memory");
    asm volatile("barrier.cluster.wait.aligned;" ::: "memory");

#pragma unroll 1
    for (int s = 0; s <= T_; s++) {
        const unsigned rb16 = (unsigned)((s & 1) * HCB);
        const unsigned wb16 = rb16 ^ (unsigned)HCB;
        const bool do0 = (s < T_);
        const bool do1 = (s >= 1);

        // ---- merged GEMMs over this warp's M-block, full K (warp-complete results) ----
#pragma unroll
        for (int nt = 0; nt < 2; nt++) {
            float a1e[4] = {0,0,0,0}, a1o[4] = {0,0,0,0};
            float a0e[4] = {0,0,0,0}, a0o[4] = {0,0,0,0};
            unsigned hb = sHCu + rb16 + hoffL + (unsigned)(nt * 8) * W1B;
#pragma unroll
            for (int kt = 0; kt < 32; kt++) {
                uint32_t b0, b1;
                ldsm_x2(b0, b1, hb + kt * 32);
                mma16816((kt & 1) ? a1o : a1e, wreg1[kt], b0, b1);
                if (kt >= 16)
                    mma16816((kt & 1) ? a0o : a0e, wreg0[kt - 16], b0, b1);
            }
            int col = nt * 8 + 2 * ctid;
            int row = wm * 16 + gid;
            sG1[row * 17 + col]           = a1e[0] + a1o[0];
            sG1[row * 17 + col + 1]       = a1e[1] + a1o[1];
            sG1[(row + 8) * 17 + col]     = a1e[2] + a1o[2];
            sG1[(row + 8) * 17 + col + 1] = a1e[3] + a1o[3];
            sG0[row * 17 + col]           = a0e[0] + a0o[0];
            sG0[row * 17 + col + 1]       = a0e[1] + a0o[1];
            sG0[(row + 8) * 17 + col]     = a0e[2] + a0o[2];
            sG0[(row + 8) * 17 + col + 1] = a0e[3] + a0o[3];
        }
        __syncwarp();   // warp-local exchange only

        // ---- cell0 + h0 publish ----
        if (do0) {
            float gi0 = xgA.x + sG0[(c0 * 4 + 0) * 17 + m];
            float gi1 = xgA.y + sG0[((c0 + 1) * 4 + 0) * 17 + m];
            float gf0 = xgA.z + sG0[(c0 * 4 + 1) * 17 + m];
            float gf1 = xgA.w + sG0[((c0 + 1) * 4 + 1) * 17 + m];
            float gg0 = xgB.x + sG0[(c0 * 4 + 2) * 17 + m];
            float gg1 = xgB.y + sG0[((c0 + 1) * 4 + 2) * 17 + m];
            float go0 = xgB.z + sG0[(c0 * 4 + 3) * 17 + m];
            float go1 = xgB.w + sG0[((c0 + 1) * 4 + 3) * 17 + m];
            c00 = sigm(gf0) * c00 + sigm(gi0) * tanhap(gg0);
            float h0 = sigm(go0) * tanhap(c00);
            c01 = sigm(gf1) * c01 + sigm(gi1) * tanhap(gg1);
            float h1 = sigm(go1) * tanhap(c01);
            __half2 hp = __floats2half2_rn(h0, h1);
            unsigned hv = *(unsigned*)&hp;
            const unsigned src_ = offx + wb16;
#pragma unroll
            for (int rr = 0; rr < CSZ; rr++) {
                unsigned ra;
                asm volatile("mapa.shared::cluster.u32 %0, %1, %2;" : "=r"(ra) : "r"(src_), "r"(rr));
                asm volatile("st.shared::cluster.u32 [%0], %1;" :: "r"(ra), "r"(hv) : "memory");
            }
        }

        // ---- cell1 + h1 publish (or final output) ----
        if (do1) {
            float gi0 = sG1[(c0 * 4 + 0) * 17 + m]       + sB1[c0 * 4 + 0];
            float gi1 = sG1[((c0 + 1) * 4 + 0) * 17 + m] + sB1[(c0 + 1) * 4 + 0];
            float gf0 = sG1[(c0 * 4 + 1) * 17 + m]       + sB1[c0 * 4 + 1];
            float gf1 = sG1[((c0 + 1) * 4 + 1) * 17 + m] + sB1[(c0 + 1) * 4 + 1];
            float gg0 = sG1[(c0 * 4 + 2) * 17 + m]       + sB1[c0 * 4 + 2];
            float gg1 = sG1[((c0 + 1) * 4 + 2) * 17 + m] + sB1[(c0 + 1) * 4 + 2];
            float go0 = sG1[(c0 * 4 + 3) * 17 + m]       + sB1[c0 * 4 + 3];
            float go1 = sG1[((c0 + 1) * 4 + 3) * 17 + m] + sB1[(c0 + 1) * 4 + 3];
            c10 = sigm(gf0) * c10 + sigm(gi0) * tanhap(gg0);
            float h0 = sigm(go0) * tanhap(c10);
            c11 = sigm(gf1) * c11 + sigm(gi1) * tanhap(gg1);
            float h1 = sigm(go1) * tanhap(c11);
            if (s < T_) {
                __half2 hp = __floats2half2_rn(h0, h1);
                unsigned hv = *(unsigned*)&hp;
                const unsigned src_ = offh + wb16;
#pragma unroll
                for (int rr = 0; rr < CSZ; rr++) {
                    unsigned ra;
                    asm volatile("mapa.shared::cluster.u32 %0, %1, %2;" : "=r"(ra) : "r"(src_), "r"(rr));
                    asm volatile("st.shared::cluster.u32 [%0], %1;" :: "r"(ra), "r"(hv) : "memory");
                }
            } else {
                g_h2last[(bm0 + m) * H_ + rank * 32 + c0]     = h0;
                g_h2last[(bm0 + m) * H_ + rank * 32 + c0 + 1] = h1;
            }
        }

        if (s < T_) {
            asm volatile("barrier.cluster.arrive.aligned;" ::: "memory");
            // prefetch xg for s+1 in the arrive->wait window (full-superstep slack)
            {
                int tn = (s + 1 < T_) ? s + 1 : s;
                xgA = xg4[xbase + (size_t)tn * 512];
                xgB = xg4[xbase + (size_t)tn * 512 + 1];
            }
            asm volatile("barrier.cluster.wait.aligned;" ::: "memory");
        }
    }
}

// ---------------- FC head (128 blocks x 2 batch rows) ----------------
__global__ void head_kernel(const float* __restrict__ W1, const float* __restrict__ b1,
                            const float* __restrict__ W2, const float* __restrict__ b2,
                            float* __restrict__ out) {
    __shared__ float sLast[2][H_];
    __shared__ float sZ[2][5 * H_ + 4];
    int b0 = blockIdx.x * 2, tid = threadIdx.x;
#pragma unroll
    for (int i = 0; i < 2; i++) sLast[i][tid] = g_h2last[(b0 + i) * H_ + tid];
    __syncthreads();
#pragma unroll
    for (int q = 0; q < 5; q++) {
        int j = q * 256 + tid;
        const float* wr = W1 + (size_t)j * H_;
        float a0 = 0.f, a1 = 0.f;
#pragma unroll 8
        for (int k = 0; k < H_; k += 4) {
            float4 w = *(const float4*)&wr[k];
            a0 += w.x * sLast[0][k] + w.y * sLast[0][k+1] + w.z * sLast[0][k+2] + w.w * sLast[0][k+3];
            a1 += w.x * sLast[1][k] + w.y * sLast[1][k+1] + w.z * sLast[1][k+2] + w.w * sLast[1][k+3];
        }
        float bb = b1[j];
        sZ[0][j] = a0 + bb; sZ[1][j] = a1 + bb;
    }
    __syncthreads();
    int w = tid >> 5, l = tid & 31;
    int b = w >> 2, o = w & 3;
    float acc = 0.f;
    for (int i = l; i < 1280; i += 32) acc += sZ[b][i] * W2[o * 1280 + i];
#pragma unroll
    for (int s = 16; s; s >>= 1) acc += __shfl_xor_sync(0xffffffffu, acc, s);
    if (l == 0) out[(b0 + b) * 4 + o] = acc + b2[o];
}

// ---------------- launch ----------------
extern "C" void kernel_launch(void* const* d_in, const int* in_sizes, int n_in,
                              void* d_out, int out_size) {
    const float* x    = (const float*)d_in[0];
    const float* Wih0 = (const float*)d_in[1];
    const float* Whh0 = (const float*)d_in[2];
    const float* bih0 = (const float*)d_in[3];
    const float* bhh0 = (const float*)d_in[4];
    const float* Wih1 = (const float*)d_in[5];
    const float* Whh1 = (const float*)d_in[6];
    const float* bih1 = (const float*)d_in[7];
    const float* bhh1 = (const float*)d_in[8];
    const float* W1   = (const float*)d_in[9];
    const float* b1   = (const float*)d_in[10];
    const float* W2   = (const float*)d_in[11];
    const float* b2   = (const float*)d_in[12];

    constexpr int SMG = NLOC * 144 + MR * 144 + (NLOC * 17 + NLOC) * 4;   // 29952
    constexpr int SMF = 133120;   // W1cat staging peak; runtime layout fits inside

    cudaFuncSetAttribute(xg_gemm64, cudaFuncAttributeMaxDynamicSharedMemorySize, SMG);
    cudaFuncSetAttribute(lstm_fused, cudaFuncAttributeMaxDynamicSharedMemorySize, SMF);

    prep_kernel<<<2048, 64>>>(Wih0, Whh0, bih0, bhh0, Wih1, Whh1, bih1, bhh1);
    xg_gemm64<<<dim3(128, T_ / TCH), 256, SMG>>>(x);
    lstm_fused<<<128, 256, SMF>>>();
    head_kernel<<<128, 256>>>(W1, b1, W2, b2, (float*)d_out);
}